// round 2
// baseline (speedup 1.0000x reference)
#include <cuda_runtime.h>

#define NN 10
#define MM 22
#define RR 2
#define NPAIR 55   // upper-triangle pairs (i<=j)

typedef unsigned long long u64;

__device__ __forceinline__ u64 pack2(float x, float y) {
    u64 r; asm("mov.b64 %0, {%1, %2};" : "=l"(r) : "f"(x), "f"(y)); return r;
}
__device__ __forceinline__ void unpack2(u64 v, float& x, float& y) {
    asm("mov.b64 {%0, %1}, %2;" : "=f"(x), "=f"(y) : "l"(v));
}
__device__ __forceinline__ u64 fma2(u64 a, u64 b, u64 c) {
    u64 d; asm("fma.rn.f32x2 %0, %1, %2, %3;" : "=l"(d) : "l"(a), "l"(b), "l"(c)); return d;
}
__device__ __forceinline__ u64 mul2(u64 a, u64 b) {
    u64 d; asm("mul.rn.f32x2 %0, %1, %2;" : "=l"(d) : "l"(a), "l"(b)); return d;
}

__device__ __forceinline__ u64 one2() { return 0x3f8000003f800000ULL; }

// Process one output row i for one batch element.
// sh[p][m] = { pack(A_r0, A_r1), pack(B_r0, B_r1) }, alpha folded into m==0.
template<int I>
__device__ __forceinline__ void do_row(const ulonglong2 (*__restrict__ sh)[MM],
                                       const u64* __restrict__ u2,
                                       float* __restrict__ op) {
    constexpr int PB = 10 * I - (I * (I - 1)) / 2 - I;   // p = PB + j
    float wv[NN];
#pragma unroll
    for (int j = 0; j < I; j++) wv[j] = 0.0f;
    float rsum = 0.0f;
#pragma unroll
    for (int j = I; j < NN; j++) {
        const ulonglong2* cp = sh[PB + j];
        u64 accA = one2(), accB = one2();   // two partial product chains (even/odd m) for ILP
#pragma unroll
        for (int m = 0; m < MM; m += 2) {
            ulonglong2 c0 = cp[m];
            ulonglong2 c1 = cp[m + 1];
            accA = mul2(accA, fma2(c0.y, u2[m],     c0.x));   // lit = B*u + A, both r at once
            accB = mul2(accB, fma2(c1.y, u2[m + 1], c1.x));
        }
        float c0f, c1f;
        unpack2(mul2(accA, accB), c0f, c1f);                  // c_r = alpha_r * clause_r
        float g  = c0f + c1f - c0f * c1f;                     // 1 - (1-c0)(1-c1)
        float gc = fmaxf(g, 1e-6f);
        float w  = gc * gc;                                   // exp(log(g)/0.5) == g^2
        wv[j] = w;
        rsum += w;
    }
    float rinv = 1.0f / rsum;
#pragma unroll
    for (int k = 0; k < NN / 2; k++)
        reinterpret_cast<float2*>(op)[k] =
            make_float2(wv[2 * k] * rinv, wv[2 * k + 1] * rinv);
}

__global__ void __launch_bounds__(256)
tl_kernel(const float* __restrict__ pred,   // (B, M)
          const float* __restrict__ sel,    // (N, N, R, M, 3)
          const float* __restrict__ alog,   // (N, N, R)
          float* __restrict__ out,          // (B, N, N)
          int B) {
    __shared__ ulonglong2 sh[NPAIR][MM];

    // ---- Build coefficients (per block; tiny redundant work, avoids 2nd kernel) ----
    for (int idx = threadIdx.x; idx < NPAIR * MM; idx += blockDim.x) {
        int p = idx / MM, m = idx - p * MM;
        int i = 0, rem = p;
        while (rem >= NN - i) { rem -= NN - i; i++; }
        int j = i + rem;
        float Av[RR], Bv[RR];
#pragma unroll
        for (int r = 0; r < RR; r++) {
            const float* s = sel + (size_t)((((i * NN + j) * RR + r) * MM + m) * 3);
            float x0 = s[0] * 1.25f, x1 = s[1] * 1.25f, x2 = s[2] * 1.25f;  // /LIT_TEMP
            float mx = fmaxf(x0, fmaxf(x1, x2));
            float e0 = __expf(x0 - mx), e1 = __expf(x1 - mx), e2 = __expf(x2 - mx);
            float inv = 1.0f / (e0 + e1 + e2);
            float s0 = e0 * inv, s1 = e1 * inv, s2 = e2 * inv;
            float A = s0 + s2, Bc = s1 - s2;
            if (m == 0) {   // fold alpha = sigmoid(alog) into the first literal
                float a = alog[(i * NN + j) * RR + r];
                float alpha = 1.0f / (1.0f + __expf(-a));
                A *= alpha; Bc *= alpha;
            }
            Av[r] = A; Bv[r] = Bc;
        }
        ulonglong2 v;
        v.x = pack2(Av[0], Av[1]);
        v.y = pack2(Bv[0], Bv[1]);
        sh[p][m] = v;
    }
    __syncthreads();

    // ---- Main compute: 2 threads per batch row (rows 0-2 vs rows 3-9) ----
    int half = threadIdx.x >> 7;                         // warps 0-3: half 0, warps 4-7: half 1
    int b = blockIdx.x * 128 + (threadIdx.x & 127);
    if (b >= B) return;

    float u[MM];
    const float2* up = reinterpret_cast<const float2*>(pred + (size_t)b * MM);  // 8B aligned
#pragma unroll
    for (int k = 0; k < MM / 2; k++) {
        float2 t = __ldg(up + k);
        u[2 * k] = t.x; u[2 * k + 1] = t.y;
    }
    u64 u2[MM];
#pragma unroll
    for (int m = 0; m < MM; m++) u2[m] = pack2(u[m], u[m]);

    float* ob = out + (size_t)b * (NN * NN);
    if (half == 0) {
        do_row<0>(sh, u2, ob + 0 * NN);
        do_row<1>(sh, u2, ob + 1 * NN);
        do_row<2>(sh, u2, ob + 2 * NN);
    } else {
        do_row<3>(sh, u2, ob + 3 * NN);
        do_row<4>(sh, u2, ob + 4 * NN);
        do_row<5>(sh, u2, ob + 5 * NN);
        do_row<6>(sh, u2, ob + 6 * NN);
        do_row<7>(sh, u2, ob + 7 * NN);
        do_row<8>(sh, u2, ob + 8 * NN);
        do_row<9>(sh, u2, ob + 9 * NN);
    }
}

extern "C" void kernel_launch(void* const* d_in, const int* in_sizes, int n_in,
                              void* d_out, int out_size) {
    const float* pred = (const float*)d_in[0];   // (B, M)
    const float* sel  = (const float*)d_in[1];   // (N, N, R, M, 3)
    const float* alog = (const float*)d_in[2];   // (N, N, R)
    float* out = (float*)d_out;                  // (B, N, N)
    int B = in_sizes[0] / MM;
    int blocks = (B + 127) / 128;                // 128 batch rows per 256-thread block
    tl_kernel<<<blocks, 256>>>(pred, sel, alog, out, B);
}